// round 16
// baseline (speedup 1.0000x reference)
#include <cuda_runtime.h>

// Problem constants
#define PLANE (8*16*128*128)   // floats per [B=8,C=16,H=128,W=128] stream

// Ping-pong stream buffers: [parity][row][stream(right,up,down)]
__device__ float g_buf[2u*4u*3u*(unsigned)PLANE];

// Grid barrier state (generation-based; g_count self-resets each barrier)
__device__ unsigned g_count = 0;
__device__ volatile unsigned g_gen = 0;

// Dynamic smem (single-buffered per chunk):
//   s_in : 16 ch x 10x18 halo tile (8x16 px tile)  11520 B
//   s_w  : [cil=16][k=9][co=48] weights            27648 B
#define IN_F 2880                  // 16*180
#define W_F  6912                  // 16*9*48
#define SMEM_TOTAL ((IN_F + W_F) * 4)   // 39168 B -> 3 CTAs/SM

__device__ __forceinline__ float* BUF(int par, int row, int st) {
    return g_buf + (((size_t)par * 4 + row) * 3 + st) * (size_t)PLANE;
}

__device__ __forceinline__ void grid_barrier(unsigned target) {
    __syncthreads();
    if (threadIdx.x == 0) {
        __threadfence();                       // release (+ L1 inval on sm_103a)
        if (atomicAdd(&g_count, 1u) == gridDim.x - 1) {
            g_count = 0;
            __threadfence();
            g_gen = target;
        } else {
            while (g_gen != target) __nanosleep(128);
        }
        __threadfence();                       // acquire
    }
    __syncthreads();
}

// Per-level tables: first cell's column, #cells, chunk-count weights.
__constant__ int L_cmin[10]  = {0,0,0,0,1,1,2,2,3,3};
__constant__ int L_ncell[10] = {1,1,2,2,2,2,2,2,1,1};
__constant__ int L_w0[10]    = {1,1,1,1,3,2,3,2,3,2};
__constant__ int L_w1[10]    = {0,0,2,3,2,3,2,3,0,0};

// Load one 4-float patch row (2x LDS.64) and dup each float into a f32x2 reg.
#define LOADROW(dst, rowptr) do {                                           \
    const float2* _rp = reinterpret_cast<const float2*>(rowptr);            \
    float2 _a = _rp[0], _b = _rp[1];                                        \
    asm("mov.b64 %0, {%1, %1};" : "=l"(dst[0]) : "f"(_a.x));                \
    asm("mov.b64 %0, {%1, %1};" : "=l"(dst[1]) : "f"(_a.y));                \
    asm("mov.b64 %0, {%1, %1};" : "=l"(dst[2]) : "f"(_b.x));                \
    asm("mov.b64 %0, {%1, %1};" : "=l"(dst[3]) : "f"(_b.y));                \
} while (0)

// One ky slab: 3 kx * 3 co-pairs * (2 rows x 2 px) = 36 FFMA2
#define KYSLAB(ky, rlo, rhi) do {                                           \
    _Pragma("unroll")                                                       \
    for (int kx = 0; kx < 3; kx++) {                                        \
        const unsigned long long* wrow =                                    \
            reinterpret_cast<const unsigned long long*>(                    \
                &s_w[(cil * 9 + (ky) * 3 + kx) * 48 + cobase]);             \
        _Pragma("unroll")                                                   \
        for (int jp = 0; jp < 3; jp++) {                                    \
            unsigned long long w = wrow[jp];                                \
            _Pragma("unroll")                                               \
            for (int px = 0; px < 2; px++) {                                \
                asm("fma.rn.f32x2 %0, %1, %2, %0;"                          \
                    : "+l"(acc[jp][0][px]) : "l"(w), "l"(rlo[px + kx]));    \
                asm("fma.rn.f32x2 %0, %1, %2, %0;"                          \
                    : "+l"(acc[jp][1][px]) : "l"(w), "l"(rhi[px + kx]));    \
            }                                                               \
        }                                                                   \
    }                                                                       \
} while (0)

// Persistent wavefront kernel (R8 scheduling), OCCUPANCY-ORIENTED layout:
// 3 CTAs/SM (24 warps). 256 threads = 8 co-groups(6 co) x 32 slots (2x2 px);
// tile = 8 rows x 16 cols. Small acc footprint (12 f32x2) => <=85 regs.
__global__ __launch_bounds__(256, 3) void encoder_persistent(
    const float* __restrict__ x, const float* __restrict__ W,
    const float* __restrict__ bias, float* __restrict__ out)
{
    extern __shared__ __align__(16) float smem[];
    float* s_in = smem;            // IN_F
    float* s_w  = smem + IN_F;     // W_F

    const int tid = threadIdx.x;
    const int cog8 = tid & 7;              // 8 co-groups of 6 channels
    const int slot = tid >> 3;             // 32 slots: 4 rows x 8 cols of 2x2 px
    const int py0  = (slot >> 3) << 1;     // 0,2,4,6
    const int px0  = (slot & 7) << 1;      // 0..14
    const int cobase = cog8 * 6;

    unsigned gen = g_gen;

    #pragma unroll 1
    for (int lvl = 0; lvl < 10; lvl++) {
        // ---- work-balanced CTA partition across this level's cells ----
        int cell_sel, local_id, nlocal;
        if (L_ncell[lvl] == 2) {
            const int w0 = L_w0[lvl], wt = w0 + L_w1[lvl];
            const int n0 = (int)(((long long)gridDim.x * w0 + (wt >> 1)) / wt);
            cell_sel = (blockIdx.x >= n0) ? 1 : 0;
            local_id = blockIdx.x - cell_sel * n0;
            nlocal   = cell_sel ? ((int)gridDim.x - n0) : n0;
        } else {
            cell_sel = 0; local_id = blockIdx.x; nlocal = gridDim.x;
        }
        const int c = L_cmin[lvl] + cell_sel;
        const int r = lvl - 2 * c;
        const int p = c & 1, q = p ^ 1;

        // ---- per-cell input/output pointers (mirrors reference wavefront) ----
        const float *i0, *i1 = nullptr, *i2 = nullptr;
        if (c == 0) {
            i0 = (r == 0) ? x : BUF(p, r - 1, 2);
        } else {
            i0 = BUF(q, r, 0);
            if (r == 0)      i1 = BUF(q, 1, 1);
            else if (r == 3) i1 = BUF(p, 2, 2);
            else { i1 = BUF(q, r + 1, 1); i2 = BUF(p, r - 1, 2); }
        }
        float* oR = (c == 3 && r == 3) ? out : BUF(p, r, 0);
        float* oU = BUF(p, r, 1);
        float* oD = BUF(p, r, 2);
        const float* Wc = W + (size_t)(c * 4 + r) * (48 * 48 * 9);
        const float* bc = bias + (c * 4 + r) * 48;
        const float* srcs[3] = {i0, i1, i2};

        // ---- sweep this CTA's tiles (1024 = 8 img x 16 tile-rows x 8 tile-cols) ----
        #pragma unroll 1
        for (int t = local_id; t < 1024; t += nlocal) {
            const int bz  = t >> 7;
            const int rem = t & 127;
            const int gy0 = (rem >> 3) << 3;    // tile-row * 8
            const int gx0 = (rem & 7) << 4;     // tile-col * 16

            unsigned long long acc[3][2][2];
            #pragma unroll
            for (int jp = 0; jp < 3; jp++)
                #pragma unroll
                for (int py = 0; py < 2; py++)
                    #pragma unroll
                    for (int px = 0; px < 2; px++)
                        acc[jp][py][px] = 0ull;

            #pragma unroll 1
            for (int chunk = 0; chunk < 3; chunk++) {
                const float* src = srcs[chunk];
                if (!src) continue;   // zero slot: skip (uniform)

                // input tile (16ch x 10x18, SAME halo) — L2-direct loads
                for (int e = tid; e < IN_F; e += 256) {
                    int ci = e / 180; int rr = e - ci * 180;
                    int ty = rr / 18; int tx = rr - ty * 18;
                    int gy = gy0 - 1 + ty, gx = gx0 - 1 + tx;
                    float v = 0.f;
                    if ((unsigned)gy < 128u && (unsigned)gx < 128u)
                        v = __ldcg(&src[((bz * 16 + ci) * 128 + gy) * 128 + gx]);
                    s_in[e] = v;
                }
                // chunk weights, transposed to [cil][k][co]
                for (int e = tid; e < W_F; e += 256) {
                    int co = e / 144; int rr = e - co * 144;
                    int cil = rr / 9; int k  = rr - cil * 9;
                    s_w[(cil * 9 + k) * 48 + co] =
                        Wc[(co * 48 + chunk * 16 + cil) * 9 + k];
                }
                __syncthreads();

                #pragma unroll 2
                for (int cil = 0; cil < 16; cil++) {
                    const float* base = &s_in[cil * 180 + py0 * 18 + px0];
                    // ky-windowed dup rows (4-wide), <=3 rows live
                    unsigned long long r0[4], r1[4], r2[4], r3[4];
                    LOADROW(r0, base);
                    LOADROW(r1, base + 18);
                    KYSLAB(0, r0, r1);
                    LOADROW(r2, base + 36);
                    KYSLAB(1, r1, r2);
                    LOADROW(r3, base + 54);
                    KYSLAB(2, r2, r3);
                }
                __syncthreads();
            }

            // ---- epilogue: bias + relu; paired STG.64 over adjacent px ----
            float* outs[3] = {oR, oU, oD};
            #pragma unroll
            for (int jp = 0; jp < 3; jp++) {
                int co0 = cobase + jp * 2;   // even; never straddles a stream boundary
                float b0 = bc[co0], b1 = bc[co0 + 1];
                int s0 = co0 >> 4, ch0 = co0 & 15;
                float* o = outs[s0];
                #pragma unroll
                for (int py = 0; py < 2; py++) {
                    float lo0, hi0, lo1, hi1;
                    asm("mov.b64 {%0, %1}, %2;" : "=f"(lo0), "=f"(hi0) : "l"(acc[jp][py][0]));
                    asm("mov.b64 {%0, %1}, %2;" : "=f"(lo1), "=f"(hi1) : "l"(acc[jp][py][1]));
                    lo0 = fmaxf(lo0 + b0, 0.f); lo1 = fmaxf(lo1 + b0, 0.f);
                    hi0 = fmaxf(hi0 + b1, 0.f); hi1 = fmaxf(hi1 + b1, 0.f);
                    int gy = gy0 + py0 + py, gx = gx0 + px0;
                    *reinterpret_cast<float2*>(&o[((bz * 16 + ch0)     * 128 + gy) * 128 + gx])
                        = make_float2(lo0, lo1);
                    *reinterpret_cast<float2*>(&o[((bz * 16 + ch0 + 1) * 128 + gy) * 128 + gx])
                        = make_float2(hi0, hi1);
                }
            }
        }

        if (lvl < 9) { ++gen; grid_barrier(gen); }
    }
}

extern "C" void kernel_launch(void* const* d_in, const int* in_sizes, int n_in,
                              void* d_out, int out_size)
{
    const float* x = (const float*)d_in[0];            // [8,16,128,128]
    const float* W = (const float*)d_in[1];            // [4,4,48,48,3,3]
    const float* b = (const float*)d_in[2];            // [4,4,48]
    float* out = (float*)d_out;                        // [8,16,128,128]

    static int nblocks = 0;
    if (!nblocks) {
        cudaFuncSetAttribute(encoder_persistent,
                             cudaFuncAttributeMaxDynamicSharedMemorySize, SMEM_TOTAL);
        int dev = 0; cudaGetDevice(&dev);
        int sms = 0; cudaDeviceGetAttribute(&sms, cudaDevAttrMultiProcessorCount, dev);
        int occ = 0;
        cudaOccupancyMaxActiveBlocksPerMultiprocessor(&occ, encoder_persistent,
                                                      256, SMEM_TOTAL);
        if (occ < 1) occ = 1;
        if (occ > 3) occ = 3;               // 3 CTAs/SM is the design point
        nblocks = sms * occ;                // all CTAs resident -> barrier is safe
    }

    encoder_persistent<<<nblocks, 256, SMEM_TOTAL>>>(x, W, b, out);
}

// round 17
// speedup vs baseline: 1.2240x; 1.2240x over previous
#include <cuda_runtime.h>

// Problem constants
#define PLANE (8*16*128*128)   // floats per [B=8,C=16,H=128,W=128] stream

// Ping-pong stream buffers: [parity][row][stream(right,up,down)]
__device__ float g_buf[2u*4u*3u*(unsigned)PLANE];

// Grid barrier state (generation-based; g_count self-resets each barrier)
__device__ unsigned g_count = 0;
__device__ volatile unsigned g_gen = 0;

// Dynamic smem: input tile + FULL per-cell weight block (R8 layout)
//   s_in : 16 ch x 18x18 halo tile                 20736 B
//   s_w  : [ci=48][k=9][co=48] transposed weights  82944 B
#define SMEM_IN_FLOATS (16 * 324)
#define SMEM_W_FLOATS  (48 * 9 * 48)
#define SMEM_TOTAL     ((SMEM_IN_FLOATS + SMEM_W_FLOATS) * 4)

#define NTHR 384

__device__ __forceinline__ float* BUF(int par, int row, int st) {
    return g_buf + (((size_t)par * 4 + row) * 3 + st) * (size_t)PLANE;
}

__device__ __forceinline__ void grid_barrier(unsigned target) {
    __syncthreads();
    if (threadIdx.x == 0) {
        __threadfence();                       // release (+ L1 inval on sm_103a)
        if (atomicAdd(&g_count, 1u) == gridDim.x - 1) {
            g_count = 0;
            __threadfence();
            g_gen = target;
        } else {
            while (g_gen != target) __nanosleep(128);
        }
        __threadfence();                       // acquire
    }
    __syncthreads();
}

// Per-level tables: first cell's column, #cells, chunk-count weights.
__constant__ int L_cmin[10]  = {0,0,0,0,1,1,2,2,3,3};
__constant__ int L_ncell[10] = {1,1,2,2,2,2,2,2,1,1};
__constant__ int L_w0[10]    = {1,1,1,1,3,2,3,2,3,2};
__constant__ int L_w1[10]    = {0,0,2,3,2,3,2,3,0,0};

// Persistent wavefront kernel. R8 scheduling + 16x16 tile, OCCUPANCY layout:
// 384 threads = 6 co-groups(8 co = 4 pairs) x 64 pixel slots (2x2 px).
// Warp = one cog x 32 slots -> weight LDS is full-warp broadcast.
// acc = 16 f32x2 (32 regs) -> <=85 regs -> 2 CTAs x 12 warps = 24 warps/SM.
__global__ __launch_bounds__(NTHR, 2) void encoder_persistent(
    const float* __restrict__ x, const float* __restrict__ W,
    const float* __restrict__ bias, float* __restrict__ out)
{
    extern __shared__ __align__(16) float smem[];
    float* s_in = smem;                    // SMEM_IN_FLOATS
    float* s_w  = smem + SMEM_IN_FLOATS;   // SMEM_W_FLOATS

    const int tid = threadIdx.x;
    const int cog = tid >> 6;              // 0..5 (whole warp shares cog)
    const int ps  = tid & 63;              // 64 pixel slots
    const int py0 = (ps >> 3) << 1, px0 = (ps & 7) << 1;
    const int cobase = cog * 8;            // 8 consecutive co (4 pairs)

    unsigned gen = g_gen;

    #pragma unroll 1
    for (int lvl = 0; lvl < 10; lvl++) {
        // ---- work-balanced CTA partition across this level's cells ----
        int cell_sel, local_id, nlocal;
        if (L_ncell[lvl] == 2) {
            const int w0 = L_w0[lvl], wt = w0 + L_w1[lvl];
            const int n0 = (int)(((long long)gridDim.x * w0 + (wt >> 1)) / wt);
            cell_sel = (blockIdx.x >= n0) ? 1 : 0;
            local_id = blockIdx.x - cell_sel * n0;
            nlocal   = cell_sel ? ((int)gridDim.x - n0) : n0;
        } else {
            cell_sel = 0; local_id = blockIdx.x; nlocal = gridDim.x;
        }
        const int c = L_cmin[lvl] + cell_sel;
        const int r = lvl - 2 * c;
        const int p = c & 1, q = p ^ 1;

        // ---- per-cell input/output pointers (mirrors reference wavefront) ----
        const float *i0, *i1 = nullptr, *i2 = nullptr;
        if (c == 0) {
            i0 = (r == 0) ? x : BUF(p, r - 1, 2);
        } else {
            i0 = BUF(q, r, 0);
            if (r == 0)      i1 = BUF(q, 1, 1);
            else if (r == 3) i1 = BUF(p, 2, 2);
            else { i1 = BUF(q, r + 1, 1); i2 = BUF(p, r - 1, 2); }
        }
        float* oR = (c == 3 && r == 3) ? out : BUF(p, r, 0);
        float* oU = BUF(p, r, 1);
        float* oD = BUF(p, r, 2);
        const float* Wc = W + (size_t)(c * 4 + r) * (48 * 48 * 9);
        const float* bc = bias + (c * 4 + r) * 48;
        const float* srcs[3] = {i0, i1, i2};

        // ---- load FULL weight block for this cell, transposed to [ci][k][co] ----
        // (synced by the first per-chunk __syncthreads below)
        for (int e = tid; e < 48 * 432; e += NTHR) {
            int co = e / 432; int rr = e - co * 432;
            int ci = rr / 9;  int k  = rr - ci * 9;
            s_w[(ci * 9 + k) * 48 + co] = Wc[(co * 48 + ci) * 9 + k];
        }

        // ---- sweep this CTA's tiles of the cell ----
        #pragma unroll 1
        for (int t = local_id; t < 512; t += nlocal) {
            const int bz  = t >> 6;
            const int gy0 = ((t >> 3) & 7) << 4;
            const int gx0 = (t & 7) << 4;

            unsigned long long acc[4][2][2];
            #pragma unroll
            for (int jp = 0; jp < 4; jp++)
                #pragma unroll
                for (int py = 0; py < 2; py++)
                    #pragma unroll
                    for (int px = 0; px < 2; px++)
                        acc[jp][py][px] = 0ull;

            #pragma unroll 1
            for (int chunk = 0; chunk < 3; chunk++) {
                const float* src = srcs[chunk];
                if (!src) continue;   // zero slot: skip (uniform)

                // input tile (16ch x 18x18, SAME halo) — L2-direct loads
                for (int e = tid; e < 16 * 324; e += NTHR) {
                    int ci = e / 324; int rr = e - ci * 324;
                    int ty = rr / 18; int tx = rr - ty * 18;
                    int gy = gy0 - 1 + ty, gx = gx0 - 1 + tx;
                    float v = 0.f;
                    if ((unsigned)gy < 128u && (unsigned)gx < 128u)
                        v = __ldcg(&src[((bz * 16 + ci) * 128 + gy) * 128 + gx]);
                    s_in[e] = v;
                }
                __syncthreads();

                #pragma unroll 4
                for (int cil = 0; cil < 16; cil++) {
                    const int ci = chunk * 16 + cil;    // global input channel
                    unsigned long long xp[16];
                    const float* base = &s_in[cil * 324 + py0 * 18 + px0];
                    #pragma unroll
                    for (int dy = 0; dy < 4; dy++)
                        #pragma unroll
                        for (int dx = 0; dx < 4; dx++) {
                            float v = base[dy * 18 + dx];
                            asm("mov.b64 %0, {%1, %1};" : "=l"(xp[dy * 4 + dx]) : "f"(v));
                        }
                    #pragma unroll
                    for (int k = 0; k < 9; k++) {
                        const int ky = k / 3, kx = k - ky * 3;
                        const unsigned long long* wrow =
                            reinterpret_cast<const unsigned long long*>(
                                &s_w[(ci * 9 + k) * 48 + cobase]);
                        #pragma unroll
                        for (int jp = 0; jp < 4; jp++) {
                            unsigned long long w = wrow[jp];   // LDS.64, warp-broadcast
                            #pragma unroll
                            for (int py = 0; py < 2; py++)
                                #pragma unroll
                                for (int px = 0; px < 2; px++)
                                    asm("fma.rn.f32x2 %0, %1, %2, %0;"
                                        : "+l"(acc[jp][py][px])
                                        : "l"(w), "l"(xp[(py + ky) * 4 + (px + kx)]));
                        }
                    }
                }
                __syncthreads();
            }

            // ---- epilogue: bias + relu; paired STG.64 over adjacent px ----
            float* outs[3] = {oR, oU, oD};
            #pragma unroll
            for (int jp = 0; jp < 4; jp++) {
                int co0 = cobase + jp * 2;   // cobase%8==0 -> pair stays in one stream
                float b0 = bc[co0], b1 = bc[co0 + 1];
                int s0 = co0 >> 4, ch0 = co0 & 15;
                float* o = outs[s0];
                #pragma unroll
                for (int py = 0; py < 2; py++) {
                    float lo0, hi0, lo1, hi1;
                    asm("mov.b64 {%0, %1}, %2;" : "=f"(lo0), "=f"(hi0) : "l"(acc[jp][py][0]));
                    asm("mov.b64 {%0, %1}, %2;" : "=f"(lo1), "=f"(hi1) : "l"(acc[jp][py][1]));
                    lo0 = fmaxf(lo0 + b0, 0.f); lo1 = fmaxf(lo1 + b0, 0.f);
                    hi0 = fmaxf(hi0 + b1, 0.f); hi1 = fmaxf(hi1 + b1, 0.f);
                    int gy = gy0 + py0 + py, gx = gx0 + px0;
                    *reinterpret_cast<float2*>(&o[((bz * 16 + ch0)     * 128 + gy) * 128 + gx])
                        = make_float2(lo0, lo1);
                    *reinterpret_cast<float2*>(&o[((bz * 16 + ch0 + 1) * 128 + gy) * 128 + gx])
                        = make_float2(hi0, hi1);
                }
            }
        }

        if (lvl < 9) { ++gen; grid_barrier(gen); }
    }
}

extern "C" void kernel_launch(void* const* d_in, const int* in_sizes, int n_in,
                              void* d_out, int out_size)
{
    const float* x = (const float*)d_in[0];            // [8,16,128,128]
    const float* W = (const float*)d_in[1];            // [4,4,48,48,3,3]
    const float* b = (const float*)d_in[2];            // [4,4,48]
    float* out = (float*)d_out;                        // [8,16,128,128]

    static int nblocks = 0;
    if (!nblocks) {
        cudaFuncSetAttribute(encoder_persistent,
                             cudaFuncAttributeMaxDynamicSharedMemorySize, SMEM_TOTAL);
        int dev = 0; cudaGetDevice(&dev);
        int sms = 0; cudaDeviceGetAttribute(&sms, cudaDevAttrMultiProcessorCount, dev);
        int occ = 0;
        cudaOccupancyMaxActiveBlocksPerMultiprocessor(&occ, encoder_persistent,
                                                      NTHR, SMEM_TOTAL);
        if (occ < 1) occ = 1;
        if (occ > 2) occ = 2;               // 2 CTAs/SM is the design point
        nblocks = sms * occ;                // all CTAs resident -> barrier is safe
    }

    encoder_persistent<<<nblocks, NTHR, SMEM_TOTAL>>>(x, W, b, out);
}